// round 15
// baseline (speedup 1.0000x reference)
#include <cuda_runtime.h>
#include <math_constants.h>
#include <stdint.h>

#define D_MODEL 768
#define NHEAD   12
#define DH      64
#define BATCH   4
#define SEQ     2048
#define M_ROWS  (BATCH*SEQ)            /* 8192 */
#define HSZ     (BATCH*NHEAD*SEQ*DH)   /* 6291456 per matrix */
#define WSZ     (D_MODEL*D_MODEL)      /* 589824 */

// Scratch (allocation-free rule: __device__ globals)
__device__ float g_QKV[3*HSZ];
__device__ float g_A[M_ROWS*D_MODEL];
__device__ float g_xt[M_ROWS*D_MODEL];
__device__ float g_Wt[4*WSZ];

// ---------------------------------------------------------------------------
// helpers
// ---------------------------------------------------------------------------
__device__ __forceinline__ unsigned f2tf(float f) {
    unsigned u;
    asm("cvt.rna.tf32.f32 %0, %1;" : "=r"(u) : "f"(f));
    return u;
}

__device__ __forceinline__ float ex2(float x) {
    float r;
    asm("ex2.approx.f32 %0, %1;" : "=f"(r) : "f"(x));
    return r;
}

__device__ __forceinline__ void mma_tf32(float* c, const unsigned* a,
                                         unsigned b0, unsigned b1) {
    asm volatile(
        "mma.sync.aligned.m16n8k8.row.col.f32.tf32.tf32.f32 "
        "{%0,%1,%2,%3}, {%4,%5,%6,%7}, {%8,%9}, {%0,%1,%2,%3};"
        : "+f"(c[0]), "+f"(c[1]), "+f"(c[2]), "+f"(c[3])
        : "r"(a[0]), "r"(a[1]), "r"(a[2]), "r"(a[3]), "r"(b0), "r"(b1));
}

__device__ __forceinline__ void cp16(void* smem, const void* gmem) {
    uint32_t sa = (uint32_t)__cvta_generic_to_shared(smem);
    asm volatile("cp.async.cg.shared.global [%0], [%1], 16;" :: "r"(sa), "l"(gmem));
}
__device__ __forceinline__ void cp_commit() {
    asm volatile("cp.async.commit_group;" ::: "memory");
}
template <int N>
__device__ __forceinline__ void cp_wait() {
    asm volatile("cp.async.wait_group %0;" :: "n"(N) : "memory");
}

// ---------------------------------------------------------------------------
// tf32 (RNA) pre-conversion kernels
// ---------------------------------------------------------------------------
__global__ __launch_bounds__(256) void cvt_tf32(const float* __restrict__ in,
                                                float* __restrict__ out, int n4)
{
    int i = blockIdx.x*256 + threadIdx.x;
    if (i < n4) {
        float4 v = ((const float4*)in)[i];
        v.x = __uint_as_float(f2tf(v.x));
        v.y = __uint_as_float(f2tf(v.y));
        v.z = __uint_as_float(f2tf(v.z));
        v.w = __uint_as_float(f2tf(v.w));
        ((float4*)out)[i] = v;
    }
}

__global__ __launch_bounds__(256) void cvt_w4(
    const float* __restrict__ w0, const float* __restrict__ w1,
    const float* __restrict__ w2, const float* __restrict__ w3,
    float* __restrict__ out)
{
    const int z = blockIdx.z;
    const float* in = (z == 0) ? w0 : (z == 1) ? w1 : (z == 2) ? w2 : w3;
    int i = blockIdx.x*256 + threadIdx.x;
    if (i < WSZ/4) {
        float4 v = ((const float4*)in)[i];
        v.x = __uint_as_float(f2tf(v.x));
        v.y = __uint_as_float(f2tf(v.y));
        v.z = __uint_as_float(f2tf(v.z));
        v.w = __uint_as_float(f2tf(v.w));
        ((float4*)(out + (size_t)z*WSZ))[i] = v;
    }
}

// ---------------------------------------------------------------------------
// TF32 GEMM: 256 thr (8 warps), block tile 128x128, warp tile 64x32,
// 2 blocks/SM. BK=32 (24 barriers), 2-stage cp.async, stride 40
// (paired LDS.64 via slot reindex; 40 % 32 == 8 -> conflict-free).
// mode 1: mat 0/1 (Q/K) head-split [B,H,S,64]; mat 2 (V) [B,H,64,S].
// ---------------------------------------------------------------------------
#define BKG   32
#define NKB   (D_MODEL/BKG)   /* 24 */
#define GST   40
#define SM_GW_OFF (2*128*GST*4)           /* 40960 */
#define SM_GEMM   (2*2*128*GST*4)         /* 81920 */
__global__ __launch_bounds__(256, 2) void gemm_tc(
    const float* __restrict__ A,
    const float* __restrict__ W0, const float* __restrict__ W1,
    const float* __restrict__ W2,
    const float* __restrict__ b0v, const float* __restrict__ b1v,
    const float* __restrict__ b2v,
    float* __restrict__ C, int mode)
{
    extern __shared__ __align__(16) char gsm[];
    float (*As)[128][GST] = (float(*)[128][GST])(gsm);
    float (*Ws)[128][GST] = (float(*)[128][GST])(gsm + SM_GW_OFF);

    const int mat = blockIdx.z;
    const float* W    = (mat == 0) ? W0 : (mat == 1 ? W1 : W2);
    const float* bias = (mat == 0) ? b0v : (mat == 1 ? b1v : b2v);
    float* Cout = (mode == 1) ? (C + (size_t)mat * HSZ) : C;

    const int t    = threadIdx.x;
    const int warp = t >> 5;
    const int lane = t & 31;
    const int lq   = lane >> 2;
    const int lj   = lane & 3;
    const int wm   = warp & 1;
    const int wn   = warp >> 1;
    const int bm   = blockIdx.y * 128;
    const int bn   = blockIdx.x * 128;

    // staging: each thread covers row t>>1, cols (t&1)*16..+15 (4 cp16/matrix)
    const int lrow = t >> 1;
    const int lc   = (t & 1) * 16;
    const float* Ap = A + (size_t)(bm + lrow) * D_MODEL + lc;
    const float* Wp = W + (size_t)(bn + lrow) * D_MODEL + lc;

    float acc[4][4][4];
    #pragma unroll
    for (int mb = 0; mb < 4; mb++)
        #pragma unroll
        for (int nb = 0; nb < 4; nb++)
            #pragma unroll
            for (int c = 0; c < 4; c++) acc[mb][nb][c] = 0.f;

    // prologue: stage 0
    #pragma unroll
    for (int c = 0; c < 4; c++) cp16(&As[0][lrow][lc + c*4], Ap + c*4);
    #pragma unroll
    for (int c = 0; c < 4; c++) cp16(&Ws[0][lrow][lc + c*4], Wp + c*4);
    cp_commit();

    for (int kb = 0; kb < NKB; kb++) {
        cp_wait<0>();
        __syncthreads();   // stage kb ready; all warps done with other buffer

        if (kb + 1 < NKB) {
            const int s1 = (kb+1) & 1;
            const int k0 = (kb+1)*BKG;
            #pragma unroll
            for (int c = 0; c < 4; c++) cp16(&As[s1][lrow][lc + c*4], Ap + k0 + c*4);
            #pragma unroll
            for (int c = 0; c < 4; c++) cp16(&Ws[s1][lrow][lc + c*4], Wp + k0 + c*4);
            cp_commit();
        }

        const int s = kb & 1;
        #pragma unroll
        for (int kk = 0; kk < BKG; kk += 8) {
            unsigned af[4][4];
            #pragma unroll
            for (int mb = 0; mb < 4; mb++) {
                const int m0 = wm*64 + mb*16;
                float2 a0 = *(const float2*)&As[s][m0+lq  ][kk+2*lj];
                float2 a1 = *(const float2*)&As[s][m0+lq+8][kk+2*lj];
                af[mb][0] = __float_as_uint(a0.x);
                af[mb][1] = __float_as_uint(a1.x);
                af[mb][2] = __float_as_uint(a0.y);
                af[mb][3] = __float_as_uint(a1.y);
            }
            #pragma unroll
            for (int nb = 0; nb < 4; nb++) {
                const int nc = wn*32 + nb*8 + lq;
                float2 bv = *(const float2*)&Ws[s][nc][kk+2*lj];
                #pragma unroll
                for (int mb = 0; mb < 4; mb++)
                    mma_tf32(acc[mb][nb], af[mb],
                             __float_as_uint(bv.x), __float_as_uint(bv.y));
            }
        }
    }

    // epilogue (C layout independent of k-slot reindex)
    #pragma unroll
    for (int mb = 0; mb < 4; mb++) {
        const int gi = bm + wm*64 + mb*16 + lq;
        const int bb = gi >> 11, ss = gi & 2047;
        #pragma unroll
        for (int nb = 0; nb < 4; nb++) {
            const int gjl = bn + wn*32 + nb*8 + 2*lj;
            const float bv0 = bias[gjl], bv1 = bias[gjl+1];
            float2 r0, r1;
            r0.x = acc[mb][nb][0] + bv0; r0.y = acc[mb][nb][1] + bv1;
            r1.x = acc[mb][nb][2] + bv0; r1.y = acc[mb][nb][3] + bv1;
            if (mode == 0) {
                *(float2*)(Cout + (size_t)gi * D_MODEL + gjl)     = r0;
                *(float2*)(Cout + (size_t)(gi+8) * D_MODEL + gjl) = r1;
            } else {
                r0.x = __uint_as_float(f2tf(r0.x));
                r0.y = __uint_as_float(f2tf(r0.y));
                r1.x = __uint_as_float(f2tf(r1.x));
                r1.y = __uint_as_float(f2tf(r1.y));
                const int h = gjl >> 6, d = gjl & 63;
                if (mat == 2) {
                    float* p = Cout + (((size_t)bb*NHEAD + h)*DH + d)*SEQ + ss;
                    p[0]       = r0.x;
                    p[SEQ]     = r0.y;
                    p[8]       = r1.x;
                    p[SEQ + 8] = r1.y;
                } else {
                    float* p = Cout + (((size_t)bb*NHEAD + h)*SEQ)*DH + d;
                    *(float2*)(p + (size_t)ss*DH)     = r0;
                    *(float2*)(p + (size_t)(ss+8)*DH) = r1;
                }
            }
        }
    }
}

// ---------------------------------------------------------------------------
// Flash attention, TF32 mma, no-max softmax. KT=64 key tiles (32 iterations,
// one barrier each; 128 mma between barriers). P-fragments built IN PLACE in
// the S accumulator array (permuted tf32 write-back) so regs stay ~121.
// 256 thr = 128 queries, warp tile 16 rows, 2 blocks/SM.
// ---------------------------------------------------------------------------
#define KT 64
#define NT (SEQ/KT)
#define KST 72
#define VTS 72
#define SM_KS   0
#define SM_VT   (SM_KS + 2*KT*KST*4)              /* 36864 */
#define SM_MS   (SM_VT + 2*DH*VTS*4)              /* +36864 = 73728 */
#define SM_ATTN (SM_MS + SEQ*4)                   /* +8192  = 81920 */

__global__ __launch_bounds__(256, 2) void attn_tc(
    const float* __restrict__ Q, const float* __restrict__ K,
    const float* __restrict__ Vt_g, const int* __restrict__ mask,
    const float* __restrict__ temp, float* __restrict__ O)
{
    extern __shared__ __align__(16) char sm[];
    float (*Ks)[KT][KST] = (float(*)[KT][KST])(sm + SM_KS);
    float (*Vt)[DH][VTS] = (float(*)[DH][VTS])(sm + SM_VT);
    int*  mS             = (int*)             (sm + SM_MS);

    const int bh = blockIdx.y;
    const int b  = bh / NHEAD, h = bh % NHEAD;
    const int q0 = blockIdx.x * 128;
    const float scale = temp[h] * 0.125f * 1.44269504f;
    const size_t base  = (size_t)bh * SEQ * DH;   // Q,K layout [S,64]
    const size_t baseV = (size_t)bh * DH * SEQ;   // V layout [64,S]

    const int t    = threadIdx.x;
    const int warp = t >> 5;
    const int lane = t & 31;
    const int lq   = lane >> 2;
    const int lj   = lane & 3;

    // staging: K tile 64 keys x 64 d -> thread (t>>2, (t&3)*16), 4 cp16;
    //          V tile 64 d x 64 keys -> same shape
    const int skey = t >> 2;          // 0..63
    const int sd0  = (t & 3) * 16;    // 0,16,32,48

    // prologue: stage tile 0 + preload mask row
    {
        const float* kp = K    + base  + (size_t)skey*DH  + sd0;
        const float* vp = Vt_g + baseV + (size_t)skey*SEQ + sd0;
        #pragma unroll
        for (int c = 0; c < 4; c++) cp16(&Ks[0][skey][sd0 + c*4], kp + c*4);
        #pragma unroll
        for (int c = 0; c < 4; c++) cp16(&Vt[0][skey][sd0 + c*4], vp + c*4);
        cp_commit();
        #pragma unroll
        for (int i = 0; i < SEQ/256; i++) mS[i*256 + t] = mask[b*SEQ + i*256 + t];
    }

    // Q in A fragments, slot-reindexed, pre-scaled (log2e folded), tf32
    unsigned qa[8][4];
    {
        const float* qp0 = Q + base + (size_t)(q0 + warp*16 + lq) * DH;
        const float* qp1 = qp0 + 8 * DH;
        #pragma unroll
        for (int ks = 0; ks < 8; ks++) {
            const int c0 = ks*8 + 2*lj;
            qa[ks][0] = f2tf(qp0[c0]   * scale);
            qa[ks][1] = f2tf(qp1[c0]   * scale);
            qa[ks][2] = f2tf(qp0[c0+1] * scale);
            qa[ks][3] = f2tf(qp1[c0+1] * scale);
        }
    }

    float ls0 = 0.f, ls1 = 0.f;
    float o[8][4];
    #pragma unroll
    for (int nb = 0; nb < 8; nb++)
        #pragma unroll
        for (int c = 0; c < 4; c++) o[nb][c] = 0.f;

    for (int kt = 0; kt < NT; kt++) {
        cp_wait<0>();
        __syncthreads();   // tile kt visible; prior reads of other buf done

        if (kt + 1 < NT) {
            const int s1 = (kt+1) & 1;
            const int k1 = (kt+1) * KT;
            const float* kp = K    + base  + (size_t)(k1 + skey)*DH + sd0;
            const float* vp = Vt_g + baseV + (size_t)skey*SEQ + k1 + sd0;
            #pragma unroll
            for (int c = 0; c < 4; c++) cp16(&Ks[s1][skey][sd0 + c*4], kp + c*4);
            #pragma unroll
            for (int c = 0; c < 4; c++) cp16(&Vt[s1][skey][sd0 + c*4], vp + c*4);
            cp_commit();
        }

        const int s  = kt & 1;
        const int k0 = kt * KT;

        // ---- S = (scale*Q) K^T : 16x64 per warp ----
        float sc[8][4];
        #pragma unroll
        for (int nb = 0; nb < 8; nb++)
            #pragma unroll
            for (int c = 0; c < 4; c++) sc[nb][c] = 0.f;

        #pragma unroll
        for (int nb = 0; nb < 8; nb++) {
            const int ncol = nb*8 + lq;
            #pragma unroll
            for (int ks = 0; ks < 8; ks++) {
                float2 kv = *(const float2*)&Ks[s][ncol][ks*8 + 2*lj];
                mma_tf32(sc[nb], qa[ks],
                         __float_as_uint(kv.x), __float_as_uint(kv.y));
            }
        }

        // ---- p = mask ? 2^s : 0, permuted tf32 write-back IN PLACE:
        //      sc[nb] becomes the PV A-fragment {p00,p10,p01,p11} ----
        #pragma unroll
        for (int nb = 0; nb < 8; nb++) {
            const int col0 = nb*8 + 2*lj;
            const int km0 = mS[k0 + col0], km1 = mS[k0 + col0 + 1];
            float p00 = km0 ? ex2(sc[nb][0]) : 0.f;
            float p01 = km1 ? ex2(sc[nb][1]) : 0.f;
            float p10 = km0 ? ex2(sc[nb][2]) : 0.f;
            float p11 = km1 ? ex2(sc[nb][3]) : 0.f;
            ls0 += p00 + p01;
            ls1 += p10 + p11;
            sc[nb][0] = __uint_as_float(f2tf(p00));
            sc[nb][1] = __uint_as_float(f2tf(p10));
            sc[nb][2] = __uint_as_float(f2tf(p01));
            sc[nb][3] = __uint_as_float(f2tf(p11));
        }

        // ---- O += P V : A-frags = sc (in regs), paired LDS.64 for Vt ----
        #pragma unroll
        for (int ks = 0; ks < 8; ks++) {
            #pragma unroll
            for (int nb = 0; nb < 8; nb++) {
                const int ncol = nb*8 + lq;
                float2 vv = *(const float2*)&Vt[s][ncol][ks*8 + 2*lj];
                mma_tf32(o[nb], (const unsigned*)sc[ks],
                         __float_as_uint(vv.x), __float_as_uint(vv.y));
            }
        }
    }

    // ---- epilogue: reduce row sums, normalize, write tf32-rounded ----
    ls0 += __shfl_xor_sync(0xffffffffu, ls0, 1);
    ls0 += __shfl_xor_sync(0xffffffffu, ls0, 2);
    ls1 += __shfl_xor_sync(0xffffffffu, ls1, 1);
    ls1 += __shfl_xor_sync(0xffffffffu, ls1, 2);
    const float inv0 = 1.0f / ls0;
    const float inv1 = 1.0f / ls1;
    const int qr = q0 + warp*16 + lq;
    float* op0 = O + ((size_t)b*SEQ + qr    )*D_MODEL + h*DH;
    float* op1 = O + ((size_t)b*SEQ + qr + 8)*D_MODEL + h*DH;
    #pragma unroll
    for (int nb = 0; nb < 8; nb++) {
        const int col = nb*8 + 2*lj;
        float2 r0c, r1c;
        r0c.x = __uint_as_float(f2tf(o[nb][0]*inv0));
        r0c.y = __uint_as_float(f2tf(o[nb][1]*inv0));
        r1c.x = __uint_as_float(f2tf(o[nb][2]*inv1));
        r1c.y = __uint_as_float(f2tf(o[nb][3]*inv1));
        *(float2*)(op0 + col) = r0c;
        *(float2*)(op1 + col) = r1c;
    }
}

// ---------------------------------------------------------------------------
extern "C" void kernel_launch(void* const* d_in, const int* in_sizes, int n_in,
                              void* d_out, int out_size)
{
    (void)in_sizes; (void)n_in; (void)out_size;
    const float* x    = (const float*)d_in[0];
    const int*   mask = (const int*)  d_in[1];
    const float* Wq   = (const float*)d_in[2];
    const float* bq   = (const float*)d_in[3];
    const float* Wk   = (const float*)d_in[4];
    const float* bk   = (const float*)d_in[5];
    const float* Wv   = (const float*)d_in[6];
    const float* bv   = (const float*)d_in[7];
    const float* Wo   = (const float*)d_in[8];
    const float* bo   = (const float*)d_in[9];
    const float* temp = (const float*)d_in[10];

    float *QKVb, *Ab, *xt, *Wt;
    cudaGetSymbolAddress((void**)&QKVb, g_QKV);
    cudaGetSymbolAddress((void**)&Ab,   g_A);
    cudaGetSymbolAddress((void**)&xt,   g_xt);
    cudaGetSymbolAddress((void**)&Wt,   g_Wt);

    static int attr_set = 0;
    if (!attr_set) {
        cudaFuncSetAttribute(attn_tc,
            cudaFuncAttributeMaxDynamicSharedMemorySize, SM_ATTN);
        cudaFuncSetAttribute(gemm_tc,
            cudaFuncAttributeMaxDynamicSharedMemorySize, SM_GEMM);
        attr_set = 1;
    }

    cvt_tf32<<<(M_ROWS*D_MODEL/4 + 255)/256, 256>>>(x, xt, M_ROWS*D_MODEL/4);
    cvt_w4<<<dim3((WSZ/4 + 255)/256, 1, 4), 256>>>(Wq, Wk, Wv, Wo, Wt);

    gemm_tc<<<dim3(D_MODEL/128, M_ROWS/128, 3), 256, SM_GEMM>>>(
        xt, Wt, Wt + WSZ, Wt + 2*WSZ, bq, bk, bv, QKVb, 1);

    attn_tc<<<dim3(SEQ/128, BATCH*NHEAD), 256, SM_ATTN>>>(
        QKVb, QKVb + HSZ, QKVb + 2*(size_t)HSZ, mask, temp, Ab);

    gemm_tc<<<dim3(D_MODEL/128, M_ROWS/128, 1), 256, SM_GEMM>>>(
        Ab, Wt + 3*WSZ, Wt + 3*WSZ, Wt + 3*WSZ, bo, bo, bo, (float*)d_out, 0);
}

// round 16
// speedup vs baseline: 1.1311x; 1.1311x over previous
#include <cuda_runtime.h>
#include <math_constants.h>
#include <stdint.h>

#define D_MODEL 768
#define NHEAD   12
#define DH      64
#define BATCH   4
#define SEQ     2048
#define M_ROWS  (BATCH*SEQ)            /* 8192 */
#define HSZ     (BATCH*NHEAD*SEQ*DH)   /* 6291456 per matrix */
#define WSZ     (D_MODEL*D_MODEL)      /* 589824 */

// Scratch (allocation-free rule: __device__ globals)
__device__ float g_QKV[3*HSZ];
__device__ float g_A[M_ROWS*D_MODEL];
__device__ float g_xt[M_ROWS*D_MODEL];
__device__ float g_Wt[4*WSZ];

// ---------------------------------------------------------------------------
// helpers
// ---------------------------------------------------------------------------
__device__ __forceinline__ unsigned f2tf(float f) {
    unsigned u;
    asm("cvt.rna.tf32.f32 %0, %1;" : "=r"(u) : "f"(f));
    return u;
}

__device__ __forceinline__ float ex2(float x) {
    float r;
    asm("ex2.approx.f32 %0, %1;" : "=f"(r) : "f"(x));
    return r;
}

__device__ __forceinline__ void mma_tf32(float* c, const unsigned* a,
                                         unsigned b0, unsigned b1) {
    asm volatile(
        "mma.sync.aligned.m16n8k8.row.col.f32.tf32.tf32.f32 "
        "{%0,%1,%2,%3}, {%4,%5,%6,%7}, {%8,%9}, {%0,%1,%2,%3};"
        : "+f"(c[0]), "+f"(c[1]), "+f"(c[2]), "+f"(c[3])
        : "r"(a[0]), "r"(a[1]), "r"(a[2]), "r"(a[3]), "r"(b0), "r"(b1));
}

__device__ __forceinline__ void cp16(void* smem, const void* gmem) {
    uint32_t sa = (uint32_t)__cvta_generic_to_shared(smem);
    asm volatile("cp.async.cg.shared.global [%0], [%1], 16;" :: "r"(sa), "l"(gmem));
}
__device__ __forceinline__ void cp_commit() {
    asm volatile("cp.async.commit_group;" ::: "memory");
}
template <int N>
__device__ __forceinline__ void cp_wait() {
    asm volatile("cp.async.wait_group %0;" :: "n"(N) : "memory");
}

// ---------------------------------------------------------------------------
// tf32 (RNA) pre-conversion kernels
// ---------------------------------------------------------------------------
__global__ __launch_bounds__(256) void cvt_tf32(const float* __restrict__ in,
                                                float* __restrict__ out, int n4)
{
    int i = blockIdx.x*256 + threadIdx.x;
    if (i < n4) {
        float4 v = ((const float4*)in)[i];
        v.x = __uint_as_float(f2tf(v.x));
        v.y = __uint_as_float(f2tf(v.y));
        v.z = __uint_as_float(f2tf(v.z));
        v.w = __uint_as_float(f2tf(v.w));
        ((float4*)out)[i] = v;
    }
}

__global__ __launch_bounds__(256) void cvt_w4(
    const float* __restrict__ w0, const float* __restrict__ w1,
    const float* __restrict__ w2, const float* __restrict__ w3,
    float* __restrict__ out)
{
    const int z = blockIdx.z;
    const float* in = (z == 0) ? w0 : (z == 1) ? w1 : (z == 2) ? w2 : w3;
    int i = blockIdx.x*256 + threadIdx.x;
    if (i < WSZ/4) {
        float4 v = ((const float4*)in)[i];
        v.x = __uint_as_float(f2tf(v.x));
        v.y = __uint_as_float(f2tf(v.y));
        v.z = __uint_as_float(f2tf(v.z));
        v.w = __uint_as_float(f2tf(v.w));
        ((float4*)(out + (size_t)z*WSZ))[i] = v;
    }
}

// ---------------------------------------------------------------------------
// TF32 GEMM (R13-exact: measured ~340us combined): 256 thr (8 warps),
// block tile 128x128, warp tile 64x32, 2 blocks/SM, BK=16, 2-stage cp.async,
// static smem stride 20. mode 1: mat 0/1 head-split [B,H,S,64]; mat 2 (V)
// TRANSPOSED [B,H,64,S].
// ---------------------------------------------------------------------------
#define NKB   (D_MODEL/16)   /* 48 */
#define AST   20
__global__ __launch_bounds__(256, 2) void gemm_tc(
    const float* __restrict__ A,
    const float* __restrict__ W0, const float* __restrict__ W1,
    const float* __restrict__ W2,
    const float* __restrict__ b0v, const float* __restrict__ b1v,
    const float* __restrict__ b2v,
    float* __restrict__ C, int mode)
{
    __shared__ __align__(16) float As[2][128][AST];
    __shared__ __align__(16) float Ws[2][128][AST];

    const int mat = blockIdx.z;
    const float* W    = (mat == 0) ? W0 : (mat == 1 ? W1 : W2);
    const float* bias = (mat == 0) ? b0v : (mat == 1 ? b1v : b2v);
    float* Cout = (mode == 1) ? (C + (size_t)mat * HSZ) : C;

    const int t    = threadIdx.x;
    const int warp = t >> 5;
    const int lane = t & 31;
    const int lq   = lane >> 2;
    const int lj   = lane & 3;
    const int wm   = warp & 1;
    const int wn   = warp >> 1;
    const int bm   = blockIdx.y * 128;
    const int bn   = blockIdx.x * 128;

    const int lrow = t >> 1;
    const int lc   = (t & 1) * 8;
    const float* Ap = A + (size_t)(bm + lrow) * D_MODEL + lc;
    const float* Wp = W + (size_t)(bn + lrow) * D_MODEL + lc;

    float acc[4][4][4];
    #pragma unroll
    for (int mb = 0; mb < 4; mb++)
        #pragma unroll
        for (int nb = 0; nb < 4; nb++)
            #pragma unroll
            for (int c = 0; c < 4; c++) acc[mb][nb][c] = 0.f;

    cp16(&As[0][lrow][lc], Ap);
    cp16(&As[0][lrow][lc+4], Ap + 4);
    cp16(&Ws[0][lrow][lc], Wp);
    cp16(&Ws[0][lrow][lc+4], Wp + 4);
    cp_commit();

    for (int kb = 0; kb < NKB; kb++) {
        cp_wait<0>();
        __syncthreads();

        if (kb + 1 < NKB) {
            const int s1 = (kb+1) & 1;
            const int k0 = (kb+1)*16;
            cp16(&As[s1][lrow][lc], Ap + k0);
            cp16(&As[s1][lrow][lc+4], Ap + k0 + 4);
            cp16(&Ws[s1][lrow][lc], Wp + k0);
            cp16(&Ws[s1][lrow][lc+4], Wp + k0 + 4);
            cp_commit();
        }

        const int s = kb & 1;
        #pragma unroll
        for (int kk = 0; kk < 16; kk += 8) {
            unsigned af[4][4];
            #pragma unroll
            for (int mb = 0; mb < 4; mb++) {
                const int m0 = wm*64 + mb*16;
                af[mb][0] = __float_as_uint(As[s][m0+lq  ][kk+lj  ]);
                af[mb][1] = __float_as_uint(As[s][m0+lq+8][kk+lj  ]);
                af[mb][2] = __float_as_uint(As[s][m0+lq  ][kk+lj+4]);
                af[mb][3] = __float_as_uint(As[s][m0+lq+8][kk+lj+4]);
            }
            #pragma unroll
            for (int nb = 0; nb < 4; nb++) {
                const int nc = wn*32 + nb*8 + lq;
                unsigned bb0 = __float_as_uint(Ws[s][nc][kk+lj  ]);
                unsigned bb1 = __float_as_uint(Ws[s][nc][kk+lj+4]);
                #pragma unroll
                for (int mb = 0; mb < 4; mb++)
                    mma_tf32(acc[mb][nb], af[mb], bb0, bb1);
            }
        }
    }

    #pragma unroll
    for (int mb = 0; mb < 4; mb++) {
        const int gi = bm + wm*64 + mb*16 + lq;
        const int bb = gi >> 11, ss = gi & 2047;
        #pragma unroll
        for (int nb = 0; nb < 4; nb++) {
            const int gjl = bn + wn*32 + nb*8 + 2*lj;
            const float bv0 = bias[gjl], bv1 = bias[gjl+1];
            float2 r0, r1;
            r0.x = acc[mb][nb][0] + bv0; r0.y = acc[mb][nb][1] + bv1;
            r1.x = acc[mb][nb][2] + bv0; r1.y = acc[mb][nb][3] + bv1;
            if (mode == 0) {
                *(float2*)(Cout + (size_t)gi * D_MODEL + gjl)     = r0;
                *(float2*)(Cout + (size_t)(gi+8) * D_MODEL + gjl) = r1;
            } else {
                r0.x = __uint_as_float(f2tf(r0.x));
                r0.y = __uint_as_float(f2tf(r0.y));
                r1.x = __uint_as_float(f2tf(r1.x));
                r1.y = __uint_as_float(f2tf(r1.y));
                const int h = gjl >> 6, d = gjl & 63;
                if (mat == 2) {
                    float* p = Cout + (((size_t)bb*NHEAD + h)*DH + d)*SEQ + ss;
                    p[0]       = r0.x;
                    p[SEQ]     = r0.y;
                    p[8]       = r1.x;
                    p[SEQ + 8] = r1.y;
                } else {
                    float* p = Cout + (((size_t)bb*NHEAD + h)*SEQ)*DH + d;
                    *(float2*)(p + (size_t)ss*DH)     = r0;
                    *(float2*)(p + (size_t)(ss+8)*DH) = r1;
                }
            }
        }
    }
}

// ---------------------------------------------------------------------------
// Flash attention: R13 base (KT=32, 256 thr, warp tile 16, P in registers)
// + DEFERRED PV: per tile, S-mma(kt) then PV-mma(kt-1) issue back-to-back
// on the tensor pipe; exp(kt) runs after, with its S-dependency already
// drained. Vt triple-buffered (PV reads tile kt-1 while kt+1 prefetches);
// Ks double-buffered. Final PV peeled after the loop.
// ---------------------------------------------------------------------------
#define KT 32
#define NT (SEQ/KT)
#define KST 72
#define VTS 40
#define SM_KS   0
#define SM_VT   (SM_KS + 2*KT*KST*4)              /* 18432 */
#define SM_MS   (SM_VT + 3*DH*VTS*4)              /* +30720 = 49152 */
#define SM_ATTN (SM_MS + SEQ*4)                   /* +8192  = 57344 */

__global__ __launch_bounds__(256, 2) void attn_tc(
    const float* __restrict__ Q, const float* __restrict__ K,
    const float* __restrict__ Vt_g, const int* __restrict__ mask,
    const float* __restrict__ temp, float* __restrict__ O)
{
    extern __shared__ __align__(16) char sm[];
    float (*Ks)[KT][KST] = (float(*)[KT][KST])(sm + SM_KS);
    float (*Vt)[DH][VTS] = (float(*)[DH][VTS])(sm + SM_VT);
    int*  mS             = (int*)             (sm + SM_MS);

    const int bh = blockIdx.y;
    const int b  = bh / NHEAD, h = bh % NHEAD;
    const int q0 = blockIdx.x * 128;
    const float scale = temp[h] * 0.125f * 1.44269504f;
    const size_t base  = (size_t)bh * SEQ * DH;   // Q,K layout [S,64]
    const size_t baseV = (size_t)bh * DH * SEQ;   // V layout [64,S]

    const int t    = threadIdx.x;
    const int warp = t >> 5;
    const int lane = t & 31;
    const int lq   = lane >> 2;
    const int lj   = lane & 3;

    const int skey = t >> 3;          // 0..31 (K staging)
    const int sd0  = (t & 7) * 8;
    const int vd   = t >> 2;          // 0..63 (V staging)
    const int vk0  = (t & 3) * 8;

    // prologue: stage tile 0 + preload mask row
    {
        const float* kp = K    + base  + (size_t)skey*DH + sd0;
        const float* vp = Vt_g + baseV + (size_t)vd*SEQ  + vk0;
        cp16(&Ks[0][skey][sd0    ], kp);
        cp16(&Ks[0][skey][sd0 + 4], kp + 4);
        cp16(&Vt[0][vd][vk0    ], vp);
        cp16(&Vt[0][vd][vk0 + 4], vp + 4);
        cp_commit();
        #pragma unroll
        for (int i = 0; i < SEQ/256; i++) mS[i*256 + t] = mask[b*SEQ + i*256 + t];
    }

    // Q in A fragments, slot-reindexed, pre-scaled (log2e folded), tf32
    unsigned qa[8][4];
    {
        const float* qp0 = Q + base + (size_t)(q0 + warp*16 + lq) * DH;
        const float* qp1 = qp0 + 8 * DH;
        #pragma unroll
        for (int ks = 0; ks < 8; ks++) {
            const int c0 = ks*8 + 2*lj;
            qa[ks][0] = f2tf(qp0[c0]   * scale);
            qa[ks][1] = f2tf(qp1[c0]   * scale);
            qa[ks][2] = f2tf(qp0[c0+1] * scale);
            qa[ks][3] = f2tf(qp1[c0+1] * scale);
        }
    }

    float ls0 = 0.f, ls1 = 0.f;
    float o[8][4];
    #pragma unroll
    for (int nb = 0; nb < 8; nb++)
        #pragma unroll
        for (int c = 0; c < 4; c++) o[nb][c] = 0.f;

    unsigned pa[4][4];   // P fragments of the PREVIOUS tile (in registers)

    int vprev = 0;       // Vt buffer index of tile kt-1 (valid for kt>0)
    for (int kt = 0; kt < NT; kt++) {
        cp_wait<0>();
        __syncthreads();   // tile kt staged; all warps done with rewritten bufs

        const int vcur = kt % 3;
        if (kt + 1 < NT) {
            const int sk1 = (kt+1) & 1;
            const int sv1 = (kt+1) % 3;
            const int k1  = (kt+1) * KT;
            const float* kp = K    + base  + (size_t)(k1 + skey)*DH + sd0;
            const float* vp = Vt_g + baseV + (size_t)vd*SEQ + k1 + vk0;
            cp16(&Ks[sk1][skey][sd0    ], kp);
            cp16(&Ks[sk1][skey][sd0 + 4], kp + 4);
            cp16(&Vt[sv1][vd][vk0    ], vp);
            cp16(&Vt[sv1][vd][vk0 + 4], vp + 4);
            cp_commit();
        }

        const int s  = kt & 1;
        const int k0 = kt * KT;

        // ---- S = (scale*Q) K^T for tile kt ----
        float sc[4][4];
        #pragma unroll
        for (int nb = 0; nb < 4; nb++)
            #pragma unroll
            for (int c = 0; c < 4; c++) sc[nb][c] = 0.f;

        #pragma unroll
        for (int nb = 0; nb < 4; nb++) {
            const int ncol = nb*8 + lq;
            #pragma unroll
            for (int ks = 0; ks < 8; ks++) {
                float2 kv = *(const float2*)&Ks[s][ncol][ks*8 + 2*lj];
                mma_tf32(sc[nb], qa[ks],
                         __float_as_uint(kv.x), __float_as_uint(kv.y));
            }
        }

        // ---- PV for tile kt-1: independent of S(kt) results, issues
        //      back-to-back with S on the tensor pipe ----
        if (kt > 0) {
            #pragma unroll
            for (int ks = 0; ks < 4; ks++) {
                #pragma unroll
                for (int nb = 0; nb < 8; nb++) {
                    const int ncol = nb*8 + lq;
                    float2 vv = *(const float2*)&Vt[vprev][ncol][ks*8 + 2*lj];
                    mma_tf32(o[nb], pa[ks],
                             __float_as_uint(vv.x), __float_as_uint(vv.y));
                }
            }
        }

        // ---- p = mask ? 2^s : 0 -> pa (PV A-frags for NEXT iteration) ----
        #pragma unroll
        for (int nb = 0; nb < 4; nb++) {
            const int col0 = nb*8 + 2*lj;
            const int km0 = mS[k0 + col0], km1 = mS[k0 + col0 + 1];
            float p00 = km0 ? ex2(sc[nb][0]) : 0.f;
            float p01 = km1 ? ex2(sc[nb][1]) : 0.f;
            float p10 = km0 ? ex2(sc[nb][2]) : 0.f;
            float p11 = km1 ? ex2(sc[nb][3]) : 0.f;
            ls0 += p00 + p01;
            ls1 += p10 + p11;
            pa[nb][0] = f2tf(p00);
            pa[nb][1] = f2tf(p10);
            pa[nb][2] = f2tf(p01);
            pa[nb][3] = f2tf(p11);
        }

        vprev = vcur;
    }

    // ---- final PV for tile NT-1 ----
    #pragma unroll
    for (int ks = 0; ks < 4; ks++) {
        #pragma unroll
        for (int nb = 0; nb < 8; nb++) {
            const int ncol = nb*8 + lq;
            float2 vv = *(const float2*)&Vt[vprev][ncol][ks*8 + 2*lj];
            mma_tf32(o[nb], pa[ks],
                     __float_as_uint(vv.x), __float_as_uint(vv.y));
        }
    }

    // ---- epilogue: reduce row sums, normalize, write tf32-rounded ----
    ls0 += __shfl_xor_sync(0xffffffffu, ls0, 1);
    ls0 += __shfl_xor_sync(0xffffffffu, ls0, 2);
    ls1 += __shfl_xor_sync(0xffffffffu, ls1, 1);
    ls1 += __shfl_xor_sync(0xffffffffu, ls1, 2);
    const float inv0 = 1.0f / ls0;
    const float inv1 = 1.0f / ls1;
    const int qr = q0 + warp*16 + lq;
    float* op0 = O + ((size_t)b*SEQ + qr    )*D_MODEL + h*DH;
    float* op1 = O + ((size_t)b*SEQ + qr + 8)*D_MODEL + h*DH;
    #pragma unroll
    for (int nb = 0; nb < 8; nb++) {
        const int col = nb*8 + 2*lj;
        float2 r0c, r1c;
        r0c.x = __uint_as_float(f2tf(o[nb][0]*inv0));
        r0c.y = __uint_as_float(f2tf(o[nb][1]*inv0));
        r1c.x = __uint_as_float(f2tf(o[nb][2]*inv1));
        r1c.y = __uint_as_float(f2tf(o[nb][3]*inv1));
        *(float2*)(op0 + col) = r0c;
        *(float2*)(op1 + col) = r1c;
    }
}

// ---------------------------------------------------------------------------
extern "C" void kernel_launch(void* const* d_in, const int* in_sizes, int n_in,
                              void* d_out, int out_size)
{
    (void)in_sizes; (void)n_in; (void)out_size;
    const float* x    = (const float*)d_in[0];
    const int*   mask = (const int*)  d_in[1];
    const float* Wq   = (const float*)d_in[2];
    const float* bq   = (const float*)d_in[3];
    const float* Wk   = (const float*)d_in[4];
    const float* bk   = (const float*)d_in[5];
    const float* Wv   = (const float*)d_in[6];
    const float* bv   = (const float*)d_in[7];
    const float* Wo   = (const float*)d_in[8];
    const float* bo   = (const float*)d_in[9];
    const float* temp = (const float*)d_in[10];

    float *QKVb, *Ab, *xt, *Wt;
    cudaGetSymbolAddress((void**)&QKVb, g_QKV);
    cudaGetSymbolAddress((void**)&Ab,   g_A);
    cudaGetSymbolAddress((void**)&xt,   g_xt);
    cudaGetSymbolAddress((void**)&Wt,   g_Wt);

    static int attr_set = 0;
    if (!attr_set) {
        cudaFuncSetAttribute(attn_tc,
            cudaFuncAttributeMaxDynamicSharedMemorySize, SM_ATTN);
        attr_set = 1;
    }

    cvt_tf32<<<(M_ROWS*D_MODEL/4 + 255)/256, 256>>>(x, xt, M_ROWS*D_MODEL/4);
    cvt_w4<<<dim3((WSZ/4 + 255)/256, 1, 4), 256>>>(Wq, Wk, Wv, Wo, Wt);

    gemm_tc<<<dim3(D_MODEL/128, M_ROWS/128, 3), 256>>>(
        xt, Wt, Wt + WSZ, Wt + 2*WSZ, bq, bk, bv, QKVb, 1);

    attn_tc<<<dim3(SEQ/128, BATCH*NHEAD), 256, SM_ATTN>>>(
        QKVb, QKVb + HSZ, QKVb + 2*(size_t)HSZ, mask, temp, Ab);

    gemm_tc<<<dim3(D_MODEL/128, M_ROWS/128, 1), 256>>>(
        Ab, Wt + 3*WSZ, Wt + 3*WSZ, Wt + 3*WSZ, bo, bo, bo, (float*)d_out, 0);
}

// round 17
// speedup vs baseline: 1.1934x; 1.0551x over previous
#include <cuda_runtime.h>
#include <math_constants.h>
#include <stdint.h>

#define D_MODEL 768
#define NHEAD   12
#define DH      64
#define BATCH   4
#define SEQ     2048
#define M_ROWS  (BATCH*SEQ)            /* 8192 */
#define HSZ     (BATCH*NHEAD*SEQ*DH)   /* 6291456 per matrix */
#define WSZ     (D_MODEL*D_MODEL)      /* 589824 */

// Scratch (allocation-free rule: __device__ globals)
__device__ float g_QKV[3*HSZ];
__device__ float g_A[M_ROWS*D_MODEL];
__device__ float g_xt[M_ROWS*D_MODEL];
__device__ float g_Wt[4*WSZ];

// ---------------------------------------------------------------------------
// helpers
// ---------------------------------------------------------------------------
__device__ __forceinline__ unsigned f2tf(float f) {
    unsigned u;
    asm("cvt.rna.tf32.f32 %0, %1;" : "=r"(u) : "f"(f));
    return u;
}

__device__ __forceinline__ float ex2(float x) {
    float r;
    asm("ex2.approx.f32 %0, %1;" : "=f"(r) : "f"(x));
    return r;
}

__device__ __forceinline__ void mma_tf32(float* c, const unsigned* a,
                                         unsigned b0, unsigned b1) {
    asm volatile(
        "mma.sync.aligned.m16n8k8.row.col.f32.tf32.tf32.f32 "
        "{%0,%1,%2,%3}, {%4,%5,%6,%7}, {%8,%9}, {%0,%1,%2,%3};"
        : "+f"(c[0]), "+f"(c[1]), "+f"(c[2]), "+f"(c[3])
        : "r"(a[0]), "r"(a[1]), "r"(a[2]), "r"(a[3]), "r"(b0), "r"(b1));
}

__device__ __forceinline__ void cp16(void* smem, const void* gmem) {
    uint32_t sa = (uint32_t)__cvta_generic_to_shared(smem);
    asm volatile("cp.async.cg.shared.global [%0], [%1], 16;" :: "r"(sa), "l"(gmem));
}
__device__ __forceinline__ void cp_commit() {
    asm volatile("cp.async.commit_group;" ::: "memory");
}
template <int N>
__device__ __forceinline__ void cp_wait() {
    asm volatile("cp.async.wait_group %0;" :: "n"(N) : "memory");
}

// ---------------------------------------------------------------------------
// tf32 (RNA) pre-conversion kernels
// ---------------------------------------------------------------------------
__global__ __launch_bounds__(256) void cvt_tf32(const float* __restrict__ in,
                                                float* __restrict__ out, int n4)
{
    int i = blockIdx.x*256 + threadIdx.x;
    if (i < n4) {
        float4 v = ((const float4*)in)[i];
        v.x = __uint_as_float(f2tf(v.x));
        v.y = __uint_as_float(f2tf(v.y));
        v.z = __uint_as_float(f2tf(v.z));
        v.w = __uint_as_float(f2tf(v.w));
        ((float4*)out)[i] = v;
    }
}

__global__ __launch_bounds__(256) void cvt_w4(
    const float* __restrict__ w0, const float* __restrict__ w1,
    const float* __restrict__ w2, const float* __restrict__ w3,
    float* __restrict__ out)
{
    const int z = blockIdx.z;
    const float* in = (z == 0) ? w0 : (z == 1) ? w1 : (z == 2) ? w2 : w3;
    int i = blockIdx.x*256 + threadIdx.x;
    if (i < WSZ/4) {
        float4 v = ((const float4*)in)[i];
        v.x = __uint_as_float(f2tf(v.x));
        v.y = __uint_as_float(f2tf(v.y));
        v.z = __uint_as_float(f2tf(v.z));
        v.w = __uint_as_float(f2tf(v.w));
        ((float4*)(out + (size_t)z*WSZ))[i] = v;
    }
}

// ---------------------------------------------------------------------------
// TF32 GEMM: 256 thr (8 warps), block tile 128x128, warp tile 64x32,
// 2 blocks/SM, BK=16, 2-stage cp.async (R13 structure). Fragment loads are
// paired LDS.64 via contraction-slot reindex (lj <-> 2lj), stride 24
// (24*lq+2lj mod 32 all distinct per half-warp -> conflict-free).
// mode 1: mat 0/1 head-split [B,H,S,64]; mat 2 (V) TRANSPOSED [B,H,64,S].
// ---------------------------------------------------------------------------
#define NKB   (D_MODEL/16)   /* 48 */
#define AST   24
#define SM_GW_OFF (2*128*AST*4)           /* 24576 */
#define SM_GEMM   (2*2*128*AST*4)         /* 49152 */
__global__ __launch_bounds__(256, 2) void gemm_tc(
    const float* __restrict__ A,
    const float* __restrict__ W0, const float* __restrict__ W1,
    const float* __restrict__ W2,
    const float* __restrict__ b0v, const float* __restrict__ b1v,
    const float* __restrict__ b2v,
    float* __restrict__ C, int mode)
{
    extern __shared__ __align__(16) char gsm[];
    float (*As)[128][AST] = (float(*)[128][AST])(gsm);
    float (*Ws)[128][AST] = (float(*)[128][AST])(gsm + SM_GW_OFF);

    const int mat = blockIdx.z;
    const float* W    = (mat == 0) ? W0 : (mat == 1 ? W1 : W2);
    const float* bias = (mat == 0) ? b0v : (mat == 1 ? b1v : b2v);
    float* Cout = (mode == 1) ? (C + (size_t)mat * HSZ) : C;

    const int t    = threadIdx.x;
    const int warp = t >> 5;
    const int lane = t & 31;
    const int lq   = lane >> 2;
    const int lj   = lane & 3;
    const int wm   = warp & 1;
    const int wn   = warp >> 1;
    const int bm   = blockIdx.y * 128;
    const int bn   = blockIdx.x * 128;

    const int lrow = t >> 1;
    const int lc   = (t & 1) * 8;
    const float* Ap = A + (size_t)(bm + lrow) * D_MODEL + lc;
    const float* Wp = W + (size_t)(bn + lrow) * D_MODEL + lc;

    float acc[4][4][4];
    #pragma unroll
    for (int mb = 0; mb < 4; mb++)
        #pragma unroll
        for (int nb = 0; nb < 4; nb++)
            #pragma unroll
            for (int c = 0; c < 4; c++) acc[mb][nb][c] = 0.f;

    cp16(&As[0][lrow][lc], Ap);
    cp16(&As[0][lrow][lc+4], Ap + 4);
    cp16(&Ws[0][lrow][lc], Wp);
    cp16(&Ws[0][lrow][lc+4], Wp + 4);
    cp_commit();

    for (int kb = 0; kb < NKB; kb++) {
        cp_wait<0>();
        __syncthreads();

        if (kb + 1 < NKB) {
            const int s1 = (kb+1) & 1;
            const int k0 = (kb+1)*16;
            cp16(&As[s1][lrow][lc], Ap + k0);
            cp16(&As[s1][lrow][lc+4], Ap + k0 + 4);
            cp16(&Ws[s1][lrow][lc], Wp + k0);
            cp16(&Ws[s1][lrow][lc+4], Wp + k0 + 4);
            cp_commit();
        }

        const int s = kb & 1;
        #pragma unroll
        for (int kk = 0; kk < 16; kk += 8) {
            unsigned af[4][4];
            #pragma unroll
            for (int mb = 0; mb < 4; mb++) {
                const int m0 = wm*64 + mb*16;
                float2 a0 = *(const float2*)&As[s][m0+lq  ][kk+2*lj];
                float2 a1 = *(const float2*)&As[s][m0+lq+8][kk+2*lj];
                af[mb][0] = __float_as_uint(a0.x);
                af[mb][1] = __float_as_uint(a1.x);
                af[mb][2] = __float_as_uint(a0.y);
                af[mb][3] = __float_as_uint(a1.y);
            }
            #pragma unroll
            for (int nb = 0; nb < 4; nb++) {
                const int nc = wn*32 + nb*8 + lq;
                float2 bv = *(const float2*)&Ws[s][nc][kk+2*lj];
                #pragma unroll
                for (int mb = 0; mb < 4; mb++)
                    mma_tf32(acc[mb][nb], af[mb],
                             __float_as_uint(bv.x), __float_as_uint(bv.y));
            }
        }
    }

    #pragma unroll
    for (int mb = 0; mb < 4; mb++) {
        const int gi = bm + wm*64 + mb*16 + lq;
        const int bb = gi >> 11, ss = gi & 2047;
        #pragma unroll
        for (int nb = 0; nb < 4; nb++) {
            const int gjl = bn + wn*32 + nb*8 + 2*lj;
            const float bv0 = bias[gjl], bv1 = bias[gjl+1];
            float2 r0, r1;
            r0.x = acc[mb][nb][0] + bv0; r0.y = acc[mb][nb][1] + bv1;
            r1.x = acc[mb][nb][2] + bv0; r1.y = acc[mb][nb][3] + bv1;
            if (mode == 0) {
                *(float2*)(Cout + (size_t)gi * D_MODEL + gjl)     = r0;
                *(float2*)(Cout + (size_t)(gi+8) * D_MODEL + gjl) = r1;
            } else {
                r0.x = __uint_as_float(f2tf(r0.x));
                r0.y = __uint_as_float(f2tf(r0.y));
                r1.x = __uint_as_float(f2tf(r1.x));
                r1.y = __uint_as_float(f2tf(r1.y));
                const int h = gjl >> 6, d = gjl & 63;
                if (mat == 2) {
                    float* p = Cout + (((size_t)bb*NHEAD + h)*DH + d)*SEQ + ss;
                    p[0]       = r0.x;
                    p[SEQ]     = r0.y;
                    p[8]       = r1.x;
                    p[SEQ + 8] = r1.y;
                } else {
                    float* p = Cout + (((size_t)bb*NHEAD + h)*SEQ)*DH + d;
                    *(float2*)(p + (size_t)ss*DH)     = r0;
                    *(float2*)(p + (size_t)(ss+8)*DH) = r1;
                }
            }
        }
    }
}

// ---------------------------------------------------------------------------
// Flash attention (R13-exact structure, 375us measured) with ONE change:
// pa fragments skip cvt.rna — raw fp32 bits fed to mma.tf32 (HW truncates to
// tf32 internally), removing 16 ALU ops from the ex2->mma critical path.
// ---------------------------------------------------------------------------
#define KT 32
#define NT (SEQ/KT)
#define KST 72
#define VTS 40
#define SM_KS   0
#define SM_VT   (SM_KS + 2*KT*KST*4)              /* 18432 */
#define SM_MS   (SM_VT + 2*DH*VTS*4)              /* +20480 = 38912 */
#define SM_ATTN (SM_MS + SEQ*4)                   /* +8192  = 47104 */

__global__ __launch_bounds__(256, 2) void attn_tc(
    const float* __restrict__ Q, const float* __restrict__ K,
    const float* __restrict__ Vt_g, const int* __restrict__ mask,
    const float* __restrict__ temp, float* __restrict__ O)
{
    extern __shared__ __align__(16) char sm[];
    float (*Ks)[KT][KST] = (float(*)[KT][KST])(sm + SM_KS);
    float (*Vt)[DH][VTS] = (float(*)[DH][VTS])(sm + SM_VT);
    int*  mS             = (int*)             (sm + SM_MS);

    const int bh = blockIdx.y;
    const int b  = bh / NHEAD, h = bh % NHEAD;
    const int q0 = blockIdx.x * 128;
    const float scale = temp[h] * 0.125f * 1.44269504f;
    const size_t base  = (size_t)bh * SEQ * DH;   // Q,K layout [S,64]
    const size_t baseV = (size_t)bh * DH * SEQ;   // V layout [64,S]

    const int t    = threadIdx.x;
    const int warp = t >> 5;
    const int lane = t & 31;
    const int lq   = lane >> 2;
    const int lj   = lane & 3;

    const int skey = t >> 3;
    const int sd0  = (t & 7) * 8;
    const int vd   = t >> 2;
    const int vk0  = (t & 3) * 8;

    {
        const float* kp = K    + base  + (size_t)skey*DH + sd0;
        const float* vp = Vt_g + baseV + (size_t)vd*SEQ  + vk0;
        cp16(&Ks[0][skey][sd0    ], kp);
        cp16(&Ks[0][skey][sd0 + 4], kp + 4);
        cp16(&Vt[0][vd][vk0    ], vp);
        cp16(&Vt[0][vd][vk0 + 4], vp + 4);
        cp_commit();
        #pragma unroll
        for (int i = 0; i < SEQ/256; i++) mS[i*256 + t] = mask[b*SEQ + i*256 + t];
    }

    unsigned qa[8][4];
    {
        const float* qp0 = Q + base + (size_t)(q0 + warp*16 + lq) * DH;
        const float* qp1 = qp0 + 8 * DH;
        #pragma unroll
        for (int ks = 0; ks < 8; ks++) {
            const int c0 = ks*8 + 2*lj;
            qa[ks][0] = f2tf(qp0[c0]   * scale);
            qa[ks][1] = f2tf(qp1[c0]   * scale);
            qa[ks][2] = f2tf(qp0[c0+1] * scale);
            qa[ks][3] = f2tf(qp1[c0+1] * scale);
        }
    }

    float ls0 = 0.f, ls1 = 0.f;
    float o[8][4];
    #pragma unroll
    for (int nb = 0; nb < 8; nb++)
        #pragma unroll
        for (int c = 0; c < 4; c++) o[nb][c] = 0.f;

    for (int kt = 0; kt < NT; kt++) {
        cp_wait<0>();
        __syncthreads();

        if (kt + 1 < NT) {
            const int s1 = (kt+1) & 1;
            const int k1 = (kt+1) * KT;
            const float* kp = K    + base  + (size_t)(k1 + skey)*DH + sd0;
            const float* vp = Vt_g + baseV + (size_t)vd*SEQ + k1 + vk0;
            cp16(&Ks[s1][skey][sd0    ], kp);
            cp16(&Ks[s1][skey][sd0 + 4], kp + 4);
            cp16(&Vt[s1][vd][vk0    ], vp);
            cp16(&Vt[s1][vd][vk0 + 4], vp + 4);
            cp_commit();
        }

        const int s  = kt & 1;
        const int k0 = kt * KT;

        // ---- S = (scale*Q) K^T : 16x32 per warp; paired LDS.64 B-frags ----
        float sc[4][4];
        #pragma unroll
        for (int nb = 0; nb < 4; nb++)
            #pragma unroll
            for (int c = 0; c < 4; c++) sc[nb][c] = 0.f;

        #pragma unroll
        for (int nb = 0; nb < 4; nb++) {
            const int ncol = nb*8 + lq;
            #pragma unroll
            for (int ks = 0; ks < 8; ks++) {
                float2 kv = *(const float2*)&Ks[s][ncol][ks*8 + 2*lj];
                mma_tf32(sc[nb], qa[ks],
                         __float_as_uint(kv.x), __float_as_uint(kv.y));
            }
        }

        // ---- p = mask ? 2^s : 0 -> PV A-frags (raw fp32; HW truncates) ----
        unsigned pa[4][4];
        #pragma unroll
        for (int nb = 0; nb < 4; nb++) {
            const int col0 = nb*8 + 2*lj;
            const int km0 = mS[k0 + col0], km1 = mS[k0 + col0 + 1];
            float p00 = km0 ? ex2(sc[nb][0]) : 0.f;
            float p01 = km1 ? ex2(sc[nb][1]) : 0.f;
            float p10 = km0 ? ex2(sc[nb][2]) : 0.f;
            float p11 = km1 ? ex2(sc[nb][3]) : 0.f;
            ls0 += p00 + p01;
            ls1 += p10 + p11;
            pa[nb][0] = __float_as_uint(p00);
            pa[nb][1] = __float_as_uint(p10);
            pa[nb][2] = __float_as_uint(p01);
            pa[nb][3] = __float_as_uint(p11);
        }

        // ---- O += P V : A-frags from registers, paired LDS.64 for Vt ----
        #pragma unroll
        for (int ks = 0; ks < 4; ks++) {
            #pragma unroll
            for (int nb = 0; nb < 8; nb++) {
                const int ncol = nb*8 + lq;
                float2 vv = *(const float2*)&Vt[s][ncol][ks*8 + 2*lj];
                mma_tf32(o[nb], pa[ks],
                         __float_as_uint(vv.x), __float_as_uint(vv.y));
            }
        }
    }

    // ---- epilogue: reduce row sums, normalize, write tf32-rounded ----
    ls0 += __shfl_xor_sync(0xffffffffu, ls0, 1);
    ls0 += __shfl_xor_sync(0xffffffffu, ls0, 2);
    ls1 += __shfl_xor_sync(0xffffffffu, ls1, 1);
    ls1 += __shfl_xor_sync(0xffffffffu, ls1, 2);
    const float inv0 = 1.0f / ls0;
    const float inv1 = 1.0f / ls1;
    const int qr = q0 + warp*16 + lq;
    float* op0 = O + ((size_t)b*SEQ + qr    )*D_MODEL + h*DH;
    float* op1 = O + ((size_t)b*SEQ + qr + 8)*D_MODEL + h*DH;
    #pragma unroll
    for (int nb = 0; nb < 8; nb++) {
        const int col = nb*8 + 2*lj;
        float2 r0c, r1c;
        r0c.x = __uint_as_float(f2tf(o[nb][0]*inv0));
        r0c.y = __uint_as_float(f2tf(o[nb][1]*inv0));
        r1c.x = __uint_as_float(f2tf(o[nb][2]*inv1));
        r1c.y = __uint_as_float(f2tf(o[nb][3]*inv1));
        *(float2*)(op0 + col) = r0c;
        *(float2*)(op1 + col) = r1c;
    }
}

// ---------------------------------------------------------------------------
extern "C" void kernel_launch(void* const* d_in, const int* in_sizes, int n_in,
                              void* d_out, int out_size)
{
    (void)in_sizes; (void)n_in; (void)out_size;
    const float* x    = (const float*)d_in[0];
    const int*   mask = (const int*)  d_in[1];
    const float* Wq   = (const float*)d_in[2];
    const float* bq   = (const float*)d_in[3];
    const float* Wk   = (const float*)d_in[4];
    const float* bk   = (const float*)d_in[5];
    const float* Wv   = (const float*)d_in[6];
    const float* bv   = (const float*)d_in[7];
    const float* Wo   = (const float*)d_in[8];
    const float* bo   = (const float*)d_in[9];
    const float* temp = (const float*)d_in[10];

    float *QKVb, *Ab, *xt, *Wt;
    cudaGetSymbolAddress((void**)&QKVb, g_QKV);
    cudaGetSymbolAddress((void**)&Ab,   g_A);
    cudaGetSymbolAddress((void**)&xt,   g_xt);
    cudaGetSymbolAddress((void**)&Wt,   g_Wt);

    static int attr_set = 0;
    if (!attr_set) {
        cudaFuncSetAttribute(attn_tc,
            cudaFuncAttributeMaxDynamicSharedMemorySize, SM_ATTN);
        cudaFuncSetAttribute(gemm_tc,
            cudaFuncAttributeMaxDynamicSharedMemorySize, SM_GEMM);
        attr_set = 1;
    }

    cvt_tf32<<<(M_ROWS*D_MODEL/4 + 255)/256, 256>>>(x, xt, M_ROWS*D_MODEL/4);
    cvt_w4<<<dim3((WSZ/4 + 255)/256, 1, 4), 256>>>(Wq, Wk, Wv, Wo, Wt);

    gemm_tc<<<dim3(D_MODEL/128, M_ROWS/128, 3), 256, SM_GEMM>>>(
        xt, Wt, Wt + WSZ, Wt + 2*WSZ, bq, bk, bv, QKVb, 1);

    attn_tc<<<dim3(SEQ/128, BATCH*NHEAD), 256, SM_ATTN>>>(
        QKVb, QKVb + HSZ, QKVb + 2*(size_t)HSZ, mask, temp, Ab);

    gemm_tc<<<dim3(D_MODEL/128, M_ROWS/128, 1), 256, SM_GEMM>>>(
        Ab, Wt + 3*WSZ, Wt + 3*WSZ, Wt + 3*WSZ, bo, bo, bo, (float*)d_out, 0);
}